// round 4
// baseline (speedup 1.0000x reference)
#include <cuda_runtime.h>
#include <cuda_bf16.h>

#define COLS  4096
#define TPB   512
#define EPT   8            // 2 x float4 per thread
#define NWARP (TPB / 32)
#define NCTA  2
#define NSM   152          // GB300

__device__ __forceinline__ float fsign(float x) {
    return (x > 0.f) ? 1.f : ((x < 0.f) ? -1.f : 0.f);
}

// Two-barrier block reduce; caller provides a dedicated smem row (no trailing
// barrier needed because each call site uses its own buffer).
__device__ __forceinline__ float block_reduce(float a, float* sw) {
    #pragma unroll
    for (int o = 16; o; o >>= 1) a += __shfl_xor_sync(0xffffffffu, a, o);
    if ((threadIdx.x & 31) == 0) sw[threadIdx.x >> 5] = a;
    __syncthreads();
    if (threadIdx.x < 32) {
        a = (threadIdx.x < NWARP) ? sw[threadIdx.x] : 0.f;
        #pragma unroll
        for (int o = NWARP / 2; o; o >>= 1) a += __shfl_xor_sync(0xffffffffu, a, o);
        if (threadIdx.x == 0) sw[0] = a;
    }
    __syncthreads();
    return sw[0];
}

__device__ __forceinline__ float2 block_reduce2(float a, float b,
                                                float* sa, float* sb) {
    #pragma unroll
    for (int o = 16; o; o >>= 1) {
        a += __shfl_xor_sync(0xffffffffu, a, o);
        b += __shfl_xor_sync(0xffffffffu, b, o);
    }
    const int w = threadIdx.x >> 5;
    if ((threadIdx.x & 31) == 0) { sa[w] = a; sb[w] = b; }
    __syncthreads();
    if (threadIdx.x < 32) {
        a = (threadIdx.x < NWARP) ? sa[threadIdx.x] : 0.f;
        b = (threadIdx.x < NWARP) ? sb[threadIdx.x] : 0.f;
        #pragma unroll
        for (int o = NWARP / 2; o; o >>= 1) {
            a += __shfl_xor_sync(0xffffffffu, a, o);
            b += __shfl_xor_sync(0xffffffffu, b, o);
        }
        if (threadIdx.x == 0) { sa[0] = a; sb[0] = b; }
    }
    __syncthreads();
    return make_float2(sa[0], sb[0]);
}

__global__ __launch_bounds__(TPB, NCTA) void braq_persist_kernel(
    const float* __restrict__ x,
    const int* __restrict__ mask,
    float* __restrict__ out,
    int rows)
{
    __shared__ float sbuf[5][NWARP];
    const int tid    = threadIdx.x;
    const int stride = gridDim.x;
    int row = blockIdx.x;
    if (row >= rows) return;

    // ---- prime the pipeline: load row 0 for this CTA ----
    float4 px0, px1; int4 pm0, pm1;
    {
        const float4* x4 = reinterpret_cast<const float4*>(x + (size_t)row * COLS);
        const int4*   m4 = reinterpret_cast<const int4*>(mask + (size_t)row * COLS);
        px0 = __ldg(&x4[tid]); px1 = __ldg(&x4[tid + TPB]);
        pm0 = __ldg(&m4[tid]); pm1 = __ldg(&m4[tid + TPB]);
    }

    while (true) {
        const int next = row + stride;

        // ---- consume prefetch buffers into v/mf, building pass-1 partials ----
        float v[EPT], mf[EPT], r2[EPT];
        float s = 0.f, c = 0.f;
        {
            const float xs[8] = {px0.x, px0.y, px0.z, px0.w,
                                 px1.x, px1.y, px1.z, px1.w};
            const int   ms[8] = {pm0.x, pm0.y, pm0.z, pm0.w,
                                 pm1.x, pm1.y, pm1.z, pm1.w};
            #pragma unroll
            for (int k = 0; k < EPT; k++) {
                const float m = (ms[k] != 0) ? 1.f : 0.f;
                mf[k] = m;
                v[k]  = xs[k] * m;
                s += v[k];
                c += m;
            }
        }

        // ---- issue next row's loads NOW; they fly through the reductions ----
        if (next < rows) {
            const float4* x4 = reinterpret_cast<const float4*>(x + (size_t)next * COLS);
            const int4*   m4 = reinterpret_cast<const int4*>(mask + (size_t)next * COLS);
            px0 = __ldg(&x4[tid]); px1 = __ldg(&x4[tid + TPB]);
            pm0 = __ldg(&m4[tid]); pm1 = __ldg(&m4[tid + TPB]);
        }

        // ---- reductions (4 barrier phases) ----
        float2 r1 = block_reduce2(s, c, sbuf[0], sbuf[1]);
        const float inv   = (r1.y > 0.f) ? (1.f / r1.y) : 0.f;  // empty-row safe
        const float mean1 = r1.x * inv;

        float a = 0.f;
        #pragma unroll
        for (int k = 0; k < EPT; k++)
            a += fabsf(v[k] - mean1) * mf[k];
        const float scale1 = block_reduce(a, sbuf[2]) * inv;

        float s2 = 0.f;
        #pragma unroll
        for (int k = 0; k < EPT; k++) {
            const float b1 = fsign(v[k] - mean1) * scale1 + mean1;
            const float r  = (v[k] - b1) * mf[k];
            v[k]  = b1;      // reuse register: v now holds b1
            r2[k] = r;
            s2 += r;
        }
        const float mean2 = block_reduce(s2, sbuf[3]) * inv;

        float a2 = 0.f;
        #pragma unroll
        for (int k = 0; k < EPT; k++)
            a2 += fabsf(r2[k] - mean2) * mf[k];
        const float scale2 = block_reduce(a2, sbuf[4]) * inv;

        // ---- store output row ----
        float4* o4 = reinterpret_cast<float4*>(out + (size_t)row * COLS);
        #pragma unroll
        for (int i = 0; i < 2; i++) {
            float t[4];
            #pragma unroll
            for (int j = 0; j < 4; j++) {
                const int k = i * 4 + j;
                t[j] = (v[k] + fsign(r2[k] - mean2) * scale2 + mean2) * mf[k];
            }
            float4 ov; ov.x = t[0]; ov.y = t[1]; ov.z = t[2]; ov.w = t[3];
            o4[tid + i * TPB] = ov;
        }

        if (next >= rows) break;
        row = next;
    }
}

extern "C" void kernel_launch(void* const* d_in, const int* in_sizes, int n_in,
                              void* d_out, int out_size) {
    const float* x    = (const float*)d_in[0];
    const int*   mask = (const int*)d_in[1];
    float*       out  = (float*)d_out;
    const int rows = in_sizes[0] / COLS;            // 11008
    int grid = NSM * NCTA;                          // persistent
    if (grid > rows) grid = rows;
    braq_persist_kernel<<<grid, TPB>>>(x, mask, out, rows);
}

// round 5
// speedup vs baseline: 1.2746x; 1.2746x over previous
#include <cuda_runtime.h>
#include <cuda_bf16.h>

#define COLS  4096
#define TPB   512
#define EPT   8            // 2 x float4 per thread
#define NWARP (TPB / 32)

__device__ __forceinline__ float fsign(float x) {
    return (x > 0.f) ? 1.f : ((x < 0.f) ? -1.f : 0.f);
}

// Block reduce of a pair, dedicated smem buffers per call site (no trailing bar).
__device__ __forceinline__ float2 block_reduce2(float a, float b,
                                                float* sa, float* sb) {
    #pragma unroll
    for (int o = 16; o; o >>= 1) {
        a += __shfl_xor_sync(0xffffffffu, a, o);
        b += __shfl_xor_sync(0xffffffffu, b, o);
    }
    const int w = threadIdx.x >> 5;
    if ((threadIdx.x & 31) == 0) { sa[w] = a; sb[w] = b; }
    __syncthreads();
    if (threadIdx.x < 32) {
        a = (threadIdx.x < NWARP) ? sa[threadIdx.x] : 0.f;
        b = (threadIdx.x < NWARP) ? sb[threadIdx.x] : 0.f;
        #pragma unroll
        for (int o = NWARP / 2; o; o >>= 1) {
            a += __shfl_xor_sync(0xffffffffu, a, o);
            b += __shfl_xor_sync(0xffffffffu, b, o);
        }
        if (threadIdx.x == 0) { sa[0] = a; sb[0] = b; }
    }
    __syncthreads();
    return make_float2(sa[0], sb[0]);
}

__device__ __forceinline__ float block_reduce(float a, float* sw) {
    #pragma unroll
    for (int o = 16; o; o >>= 1) a += __shfl_xor_sync(0xffffffffu, a, o);
    if ((threadIdx.x & 31) == 0) sw[threadIdx.x >> 5] = a;
    __syncthreads();
    if (threadIdx.x < 32) {
        a = (threadIdx.x < NWARP) ? sw[threadIdx.x] : 0.f;
        #pragma unroll
        for (int o = NWARP / 2; o; o >>= 1) a += __shfl_xor_sync(0xffffffffu, a, o);
        if (threadIdx.x == 0) sw[0] = a;
    }
    __syncthreads();
    return sw[0];
}

__global__ __launch_bounds__(TPB) void braq_order2_kernel(
    const float* __restrict__ x,
    const int* __restrict__ mask,
    float* __restrict__ out)
{
    __shared__ float sbuf[5][NWARP];
    const size_t base = (size_t)blockIdx.x * COLS;
    const float4* __restrict__ x4 = reinterpret_cast<const float4*>(x + base);
    const int4*   __restrict__ m4 = reinterpret_cast<const int4*>(mask + base);
    const int tid = threadIdx.x;

    float v[EPT];    // masked x (x * m), later reused for b1
    float mf[EPT];   // mask as float {0,1}
    float r2[EPT];   // second-order residual

    // ---- load (streaming, evict-first) + round 1 partials: sum, count ----
    float s = 0.f, c = 0.f;
    #pragma unroll
    for (int i = 0; i < EPT / 4; i++) {
        const int idx = tid + i * TPB;
        float4 xv = __ldcs(&x4[idx]);
        int4   mv = __ldcs(&m4[idx]);
        const float xs[4] = {xv.x, xv.y, xv.z, xv.w};
        const int   ms[4] = {mv.x, mv.y, mv.z, mv.w};
        #pragma unroll
        for (int j = 0; j < 4; j++) {
            const int k = i * 4 + j;
            const float m = (ms[j] != 0) ? 1.f : 0.f;
            mf[k] = m;
            v[k]  = xs[j] * m;
            s += v[k];
            c += m;
        }
    }

    float2 r1 = block_reduce2(s, c, sbuf[0], sbuf[1]);
    const float cnt   = r1.y;
    const float inv   = (cnt > 0.f) ? (1.f / cnt) : 0.f;  // empty-row safe
    const float mean1 = r1.x * inv;

    // ---- round 2: reduce (sum|c|, sum sign(c)) together ----
    float sAbs = 0.f, sSgn = 0.f;
    #pragma unroll
    for (int k = 0; k < EPT; k++) {
        const float d = v[k] - mean1;
        sAbs += fabsf(d) * mf[k];
        sSgn += fsign(d) * mf[k];
    }
    float2 rr = block_reduce2(sAbs, sSgn, sbuf[2], sbuf[3]);
    const float scale1 = rr.x * inv;
    // mean2 = mean(r2) = ((S - mean1*cnt) - scale1 * sum_sign) / cnt
    const float mean2  = (r1.x - mean1 * cnt - scale1 * rr.y) * inv;

    // ---- round 3: compute b1, r2 once; reduce sum|r2 - mean2| ----
    float a2 = 0.f;
    #pragma unroll
    for (int k = 0; k < EPT; k++) {
        const float b1 = fsign(v[k] - mean1) * scale1 + mean1;
        const float r  = (v[k] - b1) * mf[k];
        v[k]  = b1;     // reuse: v holds b1 now
        r2[k] = r;
        a2 += fabsf(r - mean2) * mf[k];
    }
    const float scale2 = block_reduce(a2, sbuf[4]) * inv;

    // ---- store (streaming): mf * (b1 + sign(r2-mean2)*scale2 + mean2) ----
    float4* __restrict__ o4 = reinterpret_cast<float4*>(out + base);
    #pragma unroll
    for (int i = 0; i < EPT / 4; i++) {
        float t[4];
        #pragma unroll
        for (int j = 0; j < 4; j++) {
            const int k = i * 4 + j;
            t[j] = (v[k] + fsign(r2[k] - mean2) * scale2 + mean2) * mf[k];
        }
        float4 ov; ov.x = t[0]; ov.y = t[1]; ov.z = t[2]; ov.w = t[3];
        __stcs(&o4[tid + i * TPB], ov);
    }
}

extern "C" void kernel_launch(void* const* d_in, const int* in_sizes, int n_in,
                              void* d_out, int out_size) {
    const float* x    = (const float*)d_in[0];
    const int*   mask = (const int*)d_in[1];
    float*       out  = (float*)d_out;
    const int rows = in_sizes[0] / COLS;   // 11008
    braq_order2_kernel<<<rows, TPB>>>(x, mask, out);
}

// round 6
// speedup vs baseline: 1.2934x; 1.0148x over previous
#include <cuda_runtime.h>
#include <cuda_bf16.h>

#define COLS  4096
#define TPB   512
#define EPT   8            // per row: 2 x float4 per thread
#define NWARP (TPB / 32)

__device__ __forceinline__ float fsign(float x) {
    return (x > 0.f) ? 1.f : ((x < 0.f) ? -1.f : 0.f);
}

// 4-value block reduction in one barrier round. s = 4 dedicated smem rows.
__device__ __forceinline__ float4 block_reduce4(float a, float b, float c, float d,
                                                float (*s)[NWARP]) {
    #pragma unroll
    for (int o = 16; o; o >>= 1) {
        a += __shfl_xor_sync(0xffffffffu, a, o);
        b += __shfl_xor_sync(0xffffffffu, b, o);
        c += __shfl_xor_sync(0xffffffffu, c, o);
        d += __shfl_xor_sync(0xffffffffu, d, o);
    }
    const int w = threadIdx.x >> 5;
    if ((threadIdx.x & 31) == 0) { s[0][w] = a; s[1][w] = b; s[2][w] = c; s[3][w] = d; }
    __syncthreads();
    if (threadIdx.x < 32) {
        const bool in = threadIdx.x < NWARP;
        a = in ? s[0][threadIdx.x] : 0.f;
        b = in ? s[1][threadIdx.x] : 0.f;
        c = in ? s[2][threadIdx.x] : 0.f;
        d = in ? s[3][threadIdx.x] : 0.f;
        #pragma unroll
        for (int o = NWARP / 2; o; o >>= 1) {
            a += __shfl_xor_sync(0xffffffffu, a, o);
            b += __shfl_xor_sync(0xffffffffu, b, o);
            c += __shfl_xor_sync(0xffffffffu, c, o);
            d += __shfl_xor_sync(0xffffffffu, d, o);
        }
        if (threadIdx.x == 0) { s[0][0] = a; s[1][0] = b; s[2][0] = c; s[3][0] = d; }
    }
    __syncthreads();
    return make_float4(s[0][0], s[1][0], s[2][0], s[3][0]);
}

__device__ __forceinline__ float2 block_reduce2(float a, float b, float (*s)[NWARP]) {
    #pragma unroll
    for (int o = 16; o; o >>= 1) {
        a += __shfl_xor_sync(0xffffffffu, a, o);
        b += __shfl_xor_sync(0xffffffffu, b, o);
    }
    const int w = threadIdx.x >> 5;
    if ((threadIdx.x & 31) == 0) { s[0][w] = a; s[1][w] = b; }
    __syncthreads();
    if (threadIdx.x < 32) {
        const bool in = threadIdx.x < NWARP;
        a = in ? s[0][threadIdx.x] : 0.f;
        b = in ? s[1][threadIdx.x] : 0.f;
        #pragma unroll
        for (int o = NWARP / 2; o; o >>= 1) {
            a += __shfl_xor_sync(0xffffffffu, a, o);
            b += __shfl_xor_sync(0xffffffffu, b, o);
        }
        if (threadIdx.x == 0) { s[0][0] = a; s[1][0] = b; }
    }
    __syncthreads();
    return make_float2(s[0][0], s[1][0]);
}

__global__ __launch_bounds__(TPB, 2) void braq_2row_kernel(
    const float* __restrict__ x,
    const int* __restrict__ mask,
    float* __restrict__ out,
    int rows)
{
    __shared__ float sbuf[10][NWARP];   // dedicated rows per reduction site
    const int tid  = threadIdx.x;
    const int rowA = 2 * blockIdx.x;
    const int rowB = rowA + 1;
    const bool hasB = rowB < rows;

    const size_t baseA = (size_t)rowA * COLS;
    const size_t baseB = hasB ? baseA + COLS : baseA;   // alias A if no B (discarded)

    const float4* xA4 = reinterpret_cast<const float4*>(x + baseA);
    const int4*   mA4 = reinterpret_cast<const int4*>(mask + baseA);
    const float4* xB4 = reinterpret_cast<const float4*>(x + baseB);
    const int4*   mB4 = reinterpret_cast<const int4*>(mask + baseB);

    // ---- one big load burst: 8 x LDG.128 per thread ----
    float4 ax0 = __ldcs(&xA4[tid]);       float4 ax1 = __ldcs(&xA4[tid + TPB]);
    int4   am0 = __ldcs(&mA4[tid]);       int4   am1 = __ldcs(&mA4[tid + TPB]);
    float4 bx0 = __ldcs(&xB4[tid]);       float4 bx1 = __ldcs(&xB4[tid + TPB]);
    int4   bm0 = __ldcs(&mB4[tid]);       int4   bm1 = __ldcs(&mB4[tid + TPB]);

    float vA[EPT], mfA[EPT], vB[EPT], mfB[EPT];
    float sA = 0.f, cA = 0.f, sB = 0.f, cB = 0.f;
    {
        const float xsA[8] = {ax0.x, ax0.y, ax0.z, ax0.w, ax1.x, ax1.y, ax1.z, ax1.w};
        const int   msA[8] = {am0.x, am0.y, am0.z, am0.w, am1.x, am1.y, am1.z, am1.w};
        const float xsB[8] = {bx0.x, bx0.y, bx0.z, bx0.w, bx1.x, bx1.y, bx1.z, bx1.w};
        const int   msB[8] = {bm0.x, bm0.y, bm0.z, bm0.w, bm1.x, bm1.y, bm1.z, bm1.w};
        #pragma unroll
        for (int k = 0; k < EPT; k++) {
            const float ma = (msA[k] != 0) ? 1.f : 0.f;
            const float mb = (msB[k] != 0) ? 1.f : 0.f;
            mfA[k] = ma;  vA[k] = xsA[k] * ma;  sA += vA[k];  cA += ma;
            mfB[k] = mb;  vB[k] = xsB[k] * mb;  sB += vB[k];  cB += mb;
        }
    }

    // ---- round 1: sums + counts (both rows, one barrier round) ----
    float4 r1 = block_reduce4(sA, cA, sB, cB, &sbuf[0]);
    const float invA   = (r1.y > 0.f) ? (1.f / r1.y) : 0.f;
    const float invB   = (r1.w > 0.f) ? (1.f / r1.w) : 0.f;
    const float mean1A = r1.x * invA;
    const float mean1B = r1.z * invB;

    // ---- round 2: sum|c| and sum sign(c) (both rows) ----
    float aAbsA = 0.f, aSgnA = 0.f, aAbsB = 0.f, aSgnB = 0.f;
    #pragma unroll
    for (int k = 0; k < EPT; k++) {
        const float dA = vA[k] - mean1A;
        const float dB = vB[k] - mean1B;
        aAbsA += fabsf(dA) * mfA[k];   aSgnA += fsign(dA) * mfA[k];
        aAbsB += fabsf(dB) * mfB[k];   aSgnB += fsign(dB) * mfB[k];
    }
    float4 r2r = block_reduce4(aAbsA, aSgnA, aAbsB, aSgnB, &sbuf[4]);
    const float scale1A = r2r.x * invA;
    const float scale1B = r2r.z * invB;
    // mean2 = ((S - mean1*cnt) - scale1 * sum_sign) / cnt  (analytic)
    const float mean2A = (r1.x - mean1A * r1.y - scale1A * r2r.y) * invA;
    const float mean2B = (r1.z - mean1B * r1.w - scale1B * r2r.w) * invB;

    // ---- round 3: sum|r2 - mean2| (recompute b1/r2; both rows) ----
    float a2A = 0.f, a2B = 0.f;
    #pragma unroll
    for (int k = 0; k < EPT; k++) {
        const float b1A = fsign(vA[k] - mean1A) * scale1A + mean1A;
        const float b1B = fsign(vB[k] - mean1B) * scale1B + mean1B;
        a2A += fabsf((vA[k] - b1A) - mean2A) * mfA[k];
        a2B += fabsf((vB[k] - b1B) - mean2B) * mfB[k];
    }
    float2 r3 = block_reduce2(a2A, a2B, &sbuf[8]);
    const float scale2A = r3.x * invA;
    const float scale2B = r3.y * invB;

    // ---- stores: recompute b1/r2 per element ----
    float4* oA4 = reinterpret_cast<float4*>(out + baseA);
    #pragma unroll
    for (int i = 0; i < 2; i++) {
        float t[4];
        #pragma unroll
        for (int j = 0; j < 4; j++) {
            const int k = i * 4 + j;
            const float b1 = fsign(vA[k] - mean1A) * scale1A + mean1A;
            const float r  = vA[k] - b1;
            t[j] = (b1 + fsign(r - mean2A) * scale2A + mean2A) * mfA[k];
        }
        float4 ov; ov.x = t[0]; ov.y = t[1]; ov.z = t[2]; ov.w = t[3];
        __stcs(&oA4[tid + i * TPB], ov);
    }
    if (hasB) {
        float4* oB4 = reinterpret_cast<float4*>(out + baseB);
        #pragma unroll
        for (int i = 0; i < 2; i++) {
            float t[4];
            #pragma unroll
            for (int j = 0; j < 4; j++) {
                const int k = i * 4 + j;
                const float b1 = fsign(vB[k] - mean1B) * scale1B + mean1B;
                const float r  = vB[k] - b1;
                t[j] = (b1 + fsign(r - mean2B) * scale2B + mean2B) * mfB[k];
            }
            float4 ov; ov.x = t[0]; ov.y = t[1]; ov.z = t[2]; ov.w = t[3];
            __stcs(&oB4[tid + i * TPB], ov);
        }
    }
}

extern "C" void kernel_launch(void* const* d_in, const int* in_sizes, int n_in,
                              void* d_out, int out_size) {
    const float* x    = (const float*)d_in[0];
    const int*   mask = (const int*)d_in[1];
    float*       out  = (float*)d_out;
    const int rows = in_sizes[0] / COLS;      // 11008
    const int grid = (rows + 1) / 2;          // 5504
    braq_2row_kernel<<<grid, TPB>>>(x, mask, out, rows);
}